// round 13
// baseline (speedup 1.0000x reference)
#include <cuda_runtime.h>

#define KTOT   1000000
#define NCOLS  70400
#define SENT   -9999999.0f
#define TPB    160           // 160 x 2 blocks/SM = 320 thr/SM at <=204 regs

typedef unsigned long long u64;

// W3/W4/b3/b4 on the constant port; W1/W2 in shared. At 4 cols/thread the
// per-warp LDC demand sits well under the fma-pipe demand.
__constant__ ulonglong2 cW3v[324];   // W3: 36 rows x 9 ulonglong2
__constant__ float      cW4f[36];
__constant__ float      cb3f[36], cb4f[1];

static __device__ __forceinline__ u64 pack2(float lo, float hi) {
    u64 r; asm("mov.b64 %0,{%1,%2};" : "=l"(r) : "f"(lo), "f"(hi)); return r;
}
static __device__ __forceinline__ void unpack2(u64 v, float& lo, float& hi) {
    asm("mov.b64 {%0,%1},%2;" : "=f"(lo), "=f"(hi) : "l"(v));
}
static __device__ __forceinline__ u64 fma2(u64 a, u64 b, u64 c) {
    u64 d; asm("fma.rn.f32x2 %0,%1,%2,%3;" : "=l"(d) : "l"(a), "l"(b), "l"(c)); return d;
}
// horizontal add of the two f32 lanes (bias pre-folded into lane 0)
static __device__ __forceinline__ float hadd(u64 v) {
    float lo, hi; unpack2(v, lo, hi);
    return lo + hi;
}
// float atomic max via sign-split integer atomics (no return -> REDG)
static __device__ __forceinline__ void atomicMaxF(float* a, float v) {
    if (v >= 0.0f) atomicMax((int*)a, __float_as_int(v));
    else           atomicMin((unsigned int*)a, __float_as_uint(v));
}

__global__ void init_out_kernel(float* out, int n) {
    int i = blockIdx.x * blockDim.x + threadIdx.x;
    if (i < n) out[i] = (i < NCOLS) ? SENT : 1.0f;   // trailing element(s) = flag
}

// Layers 1+2 for ONE column pair (2 cols packed in f32x2 lanes), h1 local.
static __device__ __forceinline__ void layers12(
    const ulonglong2* sW1, const u64* sb1,
    const ulonglong2* sW2, const u64* sW2t, const u64* sb2,
    u64 xv00, u64 xv01, u64 xv10, u64 xv11,
    u64 (&h2)[2][18])
{
    u64 h1[2][9];
    #pragma unroll
    for (int j = 0; j < 18; j += 2) {
        float ho[2][2];
        #pragma unroll
        for (int s = 0; s < 2; s++) {
            const int jj = j + s;
            ulonglong2 w = sW1[jj];
            u64 bb = sb1[jj];
            u64 a0 = fma2(w.x, xv00, bb);
            u64 a1 = fma2(w.x, xv10, bb);
            a0 = fma2(w.y, xv01, a0);
            a1 = fma2(w.y, xv11, a1);
            ho[s][0] = fmaxf(hadd(a0), 0.0f);
            ho[s][1] = fmaxf(hadd(a1), 0.0f);
        }
        h1[0][j / 2] = pack2(ho[0][0], ho[1][0]);
        h1[1][j / 2] = pack2(ho[0][1], ho[1][1]);
    }

    #pragma unroll 4
    for (int j = 0; j < 36; j += 2) {
        float ho[2][2];
        #pragma unroll
        for (int s = 0; s < 2; s++) {
            const int jj = j + s;
            u64 a0 = sb2[jj], a1 = sb2[jj];
            #pragma unroll
            for (int q = 0; q < 4; q++) {
                ulonglong2 w = sW2[jj * 4 + q];
                a0 = fma2(w.x, h1[0][2 * q], a0);
                a1 = fma2(w.x, h1[1][2 * q], a1);
                a0 = fma2(w.y, h1[0][2 * q + 1], a0);
                a1 = fma2(w.y, h1[1][2 * q + 1], a1);
            }
            u64 wt = sW2t[jj];
            a0 = fma2(wt, h1[0][8], a0);
            a1 = fma2(wt, h1[1][8], a1);
            ho[s][0] = fmaxf(hadd(a0), 0.0f);
            ho[s][1] = fmaxf(hadd(a1), 0.0f);
        }
        h2[0][j / 2] = pack2(ho[0][0], ho[1][0]);
        h2[1][j / 2] = pack2(ho[0][1], ho[1][1]);
    }
}

__global__ __launch_bounds__(TPB, 2) void mlp_scatter_kernel(
    const float* __restrict__ x,        // (4, K) row-major
    const int* __restrict__ tix,        // (K, 2) int32, col index at [2k+1]
    const float* __restrict__ W1, const float* __restrict__ b1,
    const float* __restrict__ W2, const float* __restrict__ b2,
    float* __restrict__ out)
{
    __shared__ ulonglong2 sW1[18];      // W1: 18 rows x 4 w
    __shared__ ulonglong2 sW2[144];     // W2: 36 rows x (4 x ulonglong2)
    __shared__ u64        sW2t[36];     // W2 row tails
    __shared__ u64 sb1[18], sb2[36];

    const int t = threadIdx.x;
    for (int i = t; i < 18;  i += TPB) sW1[i] = ((const ulonglong2*)W1)[i];
    for (int i = t; i < 18;  i += TPB) sb1[i] = pack2(b1[i], 0.0f);
    for (int i = t; i < 144; i += TPB) {
        int row = i >> 2, q = i & 3;
        sW2[i] = make_ulonglong2(((const u64*)W2)[row * 9 + 2 * q],
                                 ((const u64*)W2)[row * 9 + 2 * q + 1]);
    }
    for (int i = t; i < 36;  i += TPB) sW2t[i] = ((const u64*)W2)[i * 9 + 8];
    for (int i = t; i < 36;  i += TPB) sb2[i] = pack2(b2[i], 0.0f);
    __syncthreads();

    const unsigned k0 = 4u * (blockIdx.x * (unsigned)TPB + (unsigned)t);
    if (k0 >= KTOT) return;

    // 4 columns: pair A = cols k0,k0+1 ; pair B = cols k0+2,k0+3.
    float4 r0 = *reinterpret_cast<const float4*>(x + 0 * (size_t)KTOT + k0);
    float4 r1 = *reinterpret_cast<const float4*>(x + 1 * (size_t)KTOT + k0);
    float4 r2 = *reinterpret_cast<const float4*>(x + 2 * (size_t)KTOT + k0);
    float4 r3 = *reinterpret_cast<const float4*>(x + 3 * (size_t)KTOT + k0);

    // Pass A: layers 1+2 for cols k0,k0+1
    u64 h2A[2][18];
    layers12(sW1, sb1, sW2, sW2t, sb2,
             pack2(r0.x, r1.x), pack2(r2.x, r3.x),
             pack2(r0.y, r1.y), pack2(r2.y, r3.y), h2A);

    // Pass B: layers 1+2 for cols k0+2,k0+3
    u64 h2B[2][18];
    layers12(sW1, sb1, sW2, sW2t, sb2,
             pack2(r0.z, r1.z), pack2(r2.z, r3.z),
             pack2(r0.w, r1.w), pack2(r2.w, r3.w), h2B);

    // ---- Layers 3+4 fused (constant-port weights): 36 -> 36 -> 1 ----
    // One row per iteration; 4 accumulator chains (4 columns). Each constant
    // weight load feeds 4 FFMA2; W3 read exactly once per thread.
    float v0 = cb4f[0], v1 = v0, v2 = v0, v3 = v0;
    #pragma unroll 4
    for (int j = 0; j < 36; j++) {
        u64 bb = pack2(cb3f[j], 0.0f);
        u64 a0 = bb, a1 = bb, a2 = bb, a3 = bb;
        #pragma unroll
        for (int q = 0; q < 9; q++) {
            ulonglong2 w = cW3v[j * 9 + q];
            a0 = fma2(w.x, h2A[0][2 * q], a0);
            a1 = fma2(w.x, h2A[1][2 * q], a1);
            a2 = fma2(w.x, h2B[0][2 * q], a2);
            a3 = fma2(w.x, h2B[1][2 * q], a3);
            a0 = fma2(w.y, h2A[0][2 * q + 1], a0);
            a1 = fma2(w.y, h2A[1][2 * q + 1], a1);
            a2 = fma2(w.y, h2B[0][2 * q + 1], a2);
            a3 = fma2(w.y, h2B[1][2 * q + 1], a3);
        }
        float w4 = cW4f[j];
        v0 = fmaf(w4, fmaxf(hadd(a0), 0.0f), v0);
        v1 = fmaf(w4, fmaxf(hadd(a1), 0.0f), v1);
        v2 = fmaf(w4, fmaxf(hadd(a2), 0.0f), v2);
        v3 = fmaf(w4, fmaxf(hadd(a3), 0.0f), v3);
    }

    // (K,2) int32 pairs: column index at odd positions (loaded at the tail
    // so they don't occupy registers across the MLP)
    const int4 p01 = *reinterpret_cast<const int4*>(tix + 2 * (size_t)k0);
    const int4 p23 = *reinterpret_cast<const int4*>(tix + 2 * (size_t)k0 + 4);
    if ((unsigned)p01.y < NCOLS) atomicMaxF(out + p01.y, v0);
    if ((unsigned)p01.w < NCOLS) atomicMaxF(out + p01.w, v1);
    if ((unsigned)p23.y < NCOLS) atomicMaxF(out + p23.y, v2);
    if ((unsigned)p23.w < NCOLS) atomicMaxF(out + p23.w, v3);
}

extern "C" void kernel_launch(void* const* d_in, const int* in_sizes, int n_in,
                              void* d_out, int out_size) {
    const float* x   = (const float*)d_in[0];
    const int*   tix = (const int*)d_in[1];
    const float* W1 = (const float*)d_in[2];
    const float* b1 = (const float*)d_in[3];
    const float* W2 = (const float*)d_in[4];
    const float* b2 = (const float*)d_in[5];
    float* out = (float*)d_out;

    // Stage the big layer into constant memory (async D2D memcpy nodes).
    cudaMemcpyToSymbolAsync(cW3v, d_in[6], 1296 * 4, 0, cudaMemcpyDeviceToDevice);
    cudaMemcpyToSymbolAsync(cb3f, d_in[7],   36 * 4, 0, cudaMemcpyDeviceToDevice);
    cudaMemcpyToSymbolAsync(cW4f, d_in[8],   36 * 4, 0, cudaMemcpyDeviceToDevice);
    cudaMemcpyToSymbolAsync(cb4f, d_in[9],    1 * 4, 0, cudaMemcpyDeviceToDevice);

    init_out_kernel<<<(out_size + 255) / 256, 256>>>(out, out_size);

    const int nthreads = KTOT / 4;                 // 4 columns per thread
    mlp_scatter_kernel<<<(nthreads + TPB - 1) / TPB, TPB>>>(
        x, tix, W1, b1, W2, b2, out);
}

// round 14
// speedup vs baseline: 1.2094x; 1.2094x over previous
#include <cuda_runtime.h>

#define KTOT   1000000
#define NCOLS  70400
#define SENT   -9999999.0f

typedef unsigned long long u64;

// All layer-3/4 params in ONE constant struct so a single memcpy node stages
// them. W1/W2 stay on the shared (LDS) port inside the kernel.
struct CParams {
    ulonglong2 W3[324];   // 36 rows x 9 ulonglong2 (k-packed pairs)
    float      b3[36];
    float      W4[36];
    float      b4;
    float      pad[3];
};
__constant__ CParams cP;
__device__   CParams gStage;   // device staging filled by pack kernel

static __device__ __forceinline__ u64 pack2(float lo, float hi) {
    u64 r; asm("mov.b64 %0,{%1,%2};" : "=l"(r) : "f"(lo), "f"(hi)); return r;
}
static __device__ __forceinline__ void unpack2(u64 v, float& lo, float& hi) {
    asm("mov.b64 {%0,%1},%2;" : "=f"(lo), "=f"(hi) : "l"(v));
}
static __device__ __forceinline__ u64 fma2(u64 a, u64 b, u64 c) {
    u64 d; asm("fma.rn.f32x2 %0,%1,%2,%3;" : "=l"(d) : "l"(a), "l"(b), "l"(c)); return d;
}
// horizontal add of the two f32 lanes (bias pre-folded into lane 0)
static __device__ __forceinline__ float hadd(u64 v) {
    float lo, hi; unpack2(v, lo, hi);
    return lo + hi;
}
// float atomic max via sign-split integer atomics (no return -> REDG)
static __device__ __forceinline__ void atomicMaxF(float* a, float v) {
    if (v >= 0.0f) atomicMax((int*)a, __float_as_int(v));
    else           atomicMin((unsigned int*)a, __float_as_uint(v));
}

// One kernel: init output (SENTINEL + flag) AND gather W3/b3/W4/b4 into the
// staging struct (single downstream memcpy node stages constants).
__global__ void init_pack_kernel(float* out, int n,
                                 const float* __restrict__ W3,
                                 const float* __restrict__ b3,
                                 const float* __restrict__ W4,
                                 const float* __restrict__ b4) {
    int i = blockIdx.x * blockDim.x + threadIdx.x;
    if (i < n) out[i] = (i < NCOLS) ? SENT : 1.0f;
    float* sw3 = reinterpret_cast<float*>(gStage.W3);
    if (i < 1296) sw3[i] = W3[i];
    else if (i < 1332) gStage.b3[i - 1296] = b3[i - 1296];
    else if (i < 1368) gStage.W4[i - 1332] = W4[i - 1332];
    else if (i == 1368) gStage.b4 = b4[0];
}

// Layers 1+2 for ONE column pair (2 cols packed in f32x2 lanes), h1 local.
static __device__ __forceinline__ void layers12(
    const ulonglong2* sW1, const u64* sb1,
    const ulonglong2* sW2, const u64* sW2t, const u64* sb2,
    u64 xv00, u64 xv01, u64 xv10, u64 xv11,
    u64 (&h2)[2][18])
{
    u64 h1[2][9];
    #pragma unroll
    for (int j = 0; j < 18; j += 2) {
        float ho[2][2];
        #pragma unroll
        for (int s = 0; s < 2; s++) {
            const int jj = j + s;
            ulonglong2 w = sW1[jj];
            u64 bb = sb1[jj];
            u64 a0 = fma2(w.x, xv00, bb);
            u64 a1 = fma2(w.x, xv10, bb);
            a0 = fma2(w.y, xv01, a0);
            a1 = fma2(w.y, xv11, a1);
            ho[s][0] = fmaxf(hadd(a0), 0.0f);
            ho[s][1] = fmaxf(hadd(a1), 0.0f);
        }
        h1[0][j / 2] = pack2(ho[0][0], ho[1][0]);
        h1[1][j / 2] = pack2(ho[0][1], ho[1][1]);
    }

    #pragma unroll 4
    for (int j = 0; j < 36; j += 2) {
        float ho[2][2];
        #pragma unroll
        for (int s = 0; s < 2; s++) {
            const int jj = j + s;
            u64 a0 = sb2[jj], a1 = sb2[jj];
            #pragma unroll
            for (int q = 0; q < 4; q++) {
                ulonglong2 w = sW2[jj * 4 + q];
                a0 = fma2(w.x, h1[0][2 * q], a0);
                a1 = fma2(w.x, h1[1][2 * q], a1);
                a0 = fma2(w.y, h1[0][2 * q + 1], a0);
                a1 = fma2(w.y, h1[1][2 * q + 1], a1);
            }
            u64 wt = sW2t[jj];
            a0 = fma2(wt, h1[0][8], a0);
            a1 = fma2(wt, h1[1][8], a1);
            ho[s][0] = fmaxf(hadd(a0), 0.0f);
            ho[s][1] = fmaxf(hadd(a1), 0.0f);
        }
        h2[0][j / 2] = pack2(ho[0][0], ho[1][0]);
        h2[1][j / 2] = pack2(ho[0][1], ho[1][1]);
    }
}

__global__ __launch_bounds__(128) void mlp_scatter_kernel(
    const float* __restrict__ x,        // (4, K) row-major
    const int* __restrict__ tix,        // (K, 2) int32, col index at [2k+1]
    const float* __restrict__ W1, const float* __restrict__ b1,
    const float* __restrict__ W2, const float* __restrict__ b2,
    float* __restrict__ out)
{
    __shared__ ulonglong2 sW1[18];      // W1: 18 rows x 4 w
    __shared__ ulonglong2 sW2[144];     // W2: 36 rows x (4 x ulonglong2)
    __shared__ u64        sW2t[36];     // W2 row tails
    __shared__ u64 sb1[18], sb2[36];

    const int t = threadIdx.x;
    for (int i = t; i < 18;  i += 128) sW1[i] = ((const ulonglong2*)W1)[i];
    for (int i = t; i < 18;  i += 128) sb1[i] = pack2(b1[i], 0.0f);
    for (int i = t; i < 144; i += 128) {
        int row = i >> 2, q = i & 3;
        sW2[i] = make_ulonglong2(((const u64*)W2)[row * 9 + 2 * q],
                                 ((const u64*)W2)[row * 9 + 2 * q + 1]);
    }
    for (int i = t; i < 36;  i += 128) sW2t[i] = ((const u64*)W2)[i * 9 + 8];
    for (int i = t; i < 36;  i += 128) sb2[i] = pack2(b2[i], 0.0f);
    __syncthreads();

    const unsigned k0 = 4u * (blockIdx.x * 128u + (unsigned)t);
    if (k0 >= KTOT) return;

    // 4 columns: pair A = cols k0,k0+1 ; pair B = cols k0+2,k0+3.
    float4 r0 = *reinterpret_cast<const float4*>(x + 0 * (size_t)KTOT + k0);
    float4 r1 = *reinterpret_cast<const float4*>(x + 1 * (size_t)KTOT + k0);
    float4 r2 = *reinterpret_cast<const float4*>(x + 2 * (size_t)KTOT + k0);
    float4 r3 = *reinterpret_cast<const float4*>(x + 3 * (size_t)KTOT + k0);

    // Pass A: layers 1+2 for cols k0,k0+1
    u64 h2A[2][18];
    layers12(sW1, sb1, sW2, sW2t, sb2,
             pack2(r0.x, r1.x), pack2(r2.x, r3.x),
             pack2(r0.y, r1.y), pack2(r2.y, r3.y), h2A);

    // Pass B: layers 1+2 for cols k0+2,k0+3
    u64 h2B[2][18];
    layers12(sW1, sb1, sW2, sW2t, sb2,
             pack2(r0.z, r1.z), pack2(r2.z, r3.z),
             pack2(r0.w, r1.w), pack2(r2.w, r3.w), h2B);

    // ---- Layers 3+4 fused (constant-port weights): 36 -> 36 -> 1 ----
    // One row per iteration; 4 accumulator chains (4 columns). Each constant
    // weight load feeds 4 FFMA2; W3 read exactly once per thread.
    float v0 = cP.b4, v1 = v0, v2 = v0, v3 = v0;
    #pragma unroll 4
    for (int j = 0; j < 36; j++) {
        u64 bb = pack2(cP.b3[j], 0.0f);
        u64 a0 = bb, a1 = bb, a2 = bb, a3 = bb;
        #pragma unroll
        for (int q = 0; q < 9; q++) {
            ulonglong2 w = cP.W3[j * 9 + q];
            a0 = fma2(w.x, h2A[0][2 * q], a0);
            a1 = fma2(w.x, h2A[1][2 * q], a1);
            a2 = fma2(w.x, h2B[0][2 * q], a2);
            a3 = fma2(w.x, h2B[1][2 * q], a3);
            a0 = fma2(w.y, h2A[0][2 * q + 1], a0);
            a1 = fma2(w.y, h2A[1][2 * q + 1], a1);
            a2 = fma2(w.y, h2B[0][2 * q + 1], a2);
            a3 = fma2(w.y, h2B[1][2 * q + 1], a3);
        }
        float w4 = cP.W4[j];
        v0 = fmaf(w4, fmaxf(hadd(a0), 0.0f), v0);
        v1 = fmaf(w4, fmaxf(hadd(a1), 0.0f), v1);
        v2 = fmaf(w4, fmaxf(hadd(a2), 0.0f), v2);
        v3 = fmaf(w4, fmaxf(hadd(a3), 0.0f), v3);
    }

    // (K,2) int32 pairs: column index at odd positions
    const int4 p01 = *reinterpret_cast<const int4*>(tix + 2 * (size_t)k0);
    const int4 p23 = *reinterpret_cast<const int4*>(tix + 2 * (size_t)k0 + 4);
    if ((unsigned)p01.y < NCOLS) atomicMaxF(out + p01.y, v0);
    if ((unsigned)p01.w < NCOLS) atomicMaxF(out + p01.w, v1);
    if ((unsigned)p23.y < NCOLS) atomicMaxF(out + p23.y, v2);
    if ((unsigned)p23.w < NCOLS) atomicMaxF(out + p23.w, v3);
}

extern "C" void kernel_launch(void* const* d_in, const int* in_sizes, int n_in,
                              void* d_out, int out_size) {
    const float* x   = (const float*)d_in[0];
    const int*   tix = (const int*)d_in[1];
    const float* W1 = (const float*)d_in[2];
    const float* b1 = (const float*)d_in[3];
    const float* W2 = (const float*)d_in[4];
    const float* b2 = (const float*)d_in[5];
    const float* W3 = (const float*)d_in[6];
    const float* b3 = (const float*)d_in[7];
    const float* W4 = (const float*)d_in[8];
    const float* b4 = (const float*)d_in[9];
    float* out = (float*)d_out;

    // Node 1: init output + gather layer-3/4 params into device staging.
    int nInit = out_size > 1369 ? out_size : 1369;
    init_pack_kernel<<<(nInit + 255) / 256, 256>>>(out, out_size, W3, b3, W4, b4);

    // Node 2: ONE memcpy staging -> constant bank.
    void* stageAddr = nullptr;
    cudaGetSymbolAddress(&stageAddr, gStage);
    cudaMemcpyToSymbolAsync(cP, stageAddr, sizeof(CParams), 0,
                            cudaMemcpyDeviceToDevice);

    // Node 3: main kernel.
    const int nthreads = KTOT / 4;                 // 4 columns per thread
    mlp_scatter_kernel<<<(nthreads + 127) / 128, 128>>>(
        x, tix, W1, b1, W2, b2, out);
}

// round 15
// speedup vs baseline: 1.2698x; 1.0499x over previous
#include <cuda_runtime.h>

#define KTOT   1000000
#define NCOLS  70400
#define SENT   -9999999.0f

typedef unsigned long long u64;

// All layer-3/4 params in ONE constant struct so a single memcpy node stages
// them. W1/W2 stay on the shared (LDS) port inside the kernel.
struct CParams {
    ulonglong2 W3[324];   // 36 rows x 9 ulonglong2 (k-packed pairs)
    float      b3[36];
    float      W4[36];
    float      b4;
    float      pad[3];
};
__constant__ CParams cP;
__device__   CParams gStage;   // device staging filled by pack kernel

static __device__ __forceinline__ u64 pack2(float lo, float hi) {
    u64 r; asm("mov.b64 %0,{%1,%2};" : "=l"(r) : "f"(lo), "f"(hi)); return r;
}
static __device__ __forceinline__ void unpack2(u64 v, float& lo, float& hi) {
    asm("mov.b64 {%0,%1},%2;" : "=f"(lo), "=f"(hi) : "l"(v));
}
static __device__ __forceinline__ u64 fma2(u64 a, u64 b, u64 c) {
    u64 d; asm("fma.rn.f32x2 %0,%1,%2,%3;" : "=l"(d) : "l"(a), "l"(b), "l"(c)); return d;
}
// horizontal add of the two f32 lanes (bias pre-folded into lane 0)
static __device__ __forceinline__ float hadd(u64 v) {
    float lo, hi; unpack2(v, lo, hi);
    return lo + hi;
}
// float atomic max via sign-split integer atomics (no return -> REDG)
static __device__ __forceinline__ void atomicMaxF(float* a, float v) {
    if (v >= 0.0f) atomicMax((int*)a, __float_as_int(v));
    else           atomicMin((unsigned int*)a, __float_as_uint(v));
}

// One kernel: init output (SENTINEL + flag) AND gather W3/b3/W4/b4 into the
// staging struct (single downstream memcpy node stages constants).
__global__ void init_pack_kernel(float* out, int n,
                                 const float* __restrict__ W3,
                                 const float* __restrict__ b3,
                                 const float* __restrict__ W4,
                                 const float* __restrict__ b4) {
    int i = blockIdx.x * blockDim.x + threadIdx.x;
    if (i < n) out[i] = (i < NCOLS) ? SENT : 1.0f;
    float* sw3 = reinterpret_cast<float*>(gStage.W3);
    if (i < 1296) sw3[i] = W3[i];
    else if (i < 1332) gStage.b3[i - 1296] = b3[i - 1296];
    else if (i < 1368) gStage.W4[i - 1332] = W4[i - 1332];
    else if (i == 1368) gStage.b4 = b4[0];
}

__global__ __launch_bounds__(128) void mlp_scatter_kernel(
    const float* __restrict__ x,        // (4, K) row-major
    const int* __restrict__ tix,        // (K, 2) int32, col index at [2k+1]
    const float* __restrict__ W1, const float* __restrict__ b1,
    const float* __restrict__ W2, const float* __restrict__ b2,
    float* __restrict__ out)
{
    __shared__ ulonglong2 sW1[18];      // W1: 18 rows x 4 w
    __shared__ ulonglong2 sW2[144];     // W2: 36 rows x (4 x ulonglong2)
    __shared__ u64        sW2t[36];     // W2 row tails
    __shared__ u64 sb1[18], sb2[36];

    const int t = threadIdx.x;
    for (int i = t; i < 18;  i += 128) sW1[i] = ((const ulonglong2*)W1)[i];
    for (int i = t; i < 18;  i += 128) sb1[i] = pack2(b1[i], 0.0f);
    for (int i = t; i < 144; i += 128) {
        int row = i >> 2, q = i & 3;
        sW2[i] = make_ulonglong2(((const u64*)W2)[row * 9 + 2 * q],
                                 ((const u64*)W2)[row * 9 + 2 * q + 1]);
    }
    for (int i = t; i < 36;  i += 128) sW2t[i] = ((const u64*)W2)[i * 9 + 8];
    for (int i = t; i < 36;  i += 128) sb2[i] = pack2(b2[i], 0.0f);
    __syncthreads();

    const unsigned k0 = 4u * (blockIdx.x * 128u + (unsigned)t);
    if (k0 >= KTOT) return;

    // 4 columns: pair A = cols k0,k0+1 ; pair B = cols k0+2,k0+3.
    float4 r0 = *reinterpret_cast<const float4*>(x + 0 * (size_t)KTOT + k0);
    float4 r1 = *reinterpret_cast<const float4*>(x + 1 * (size_t)KTOT + k0);
    float4 r2 = *reinterpret_cast<const float4*>(x + 2 * (size_t)KTOT + k0);
    float4 r3 = *reinterpret_cast<const float4*>(x + 3 * (size_t)KTOT + k0);
    u64 xA0 = pack2(r0.x, r1.x), xA1 = pack2(r2.x, r3.x);
    u64 xA2 = pack2(r0.y, r1.y), xA3 = pack2(r2.y, r3.y);
    u64 xB0 = pack2(r0.z, r1.z), xB1 = pack2(r2.z, r3.z);
    u64 xB2 = pack2(r0.w, r1.w), xB3 = pack2(r2.w, r3.w);

    // ---- Layer 1: 4 -> 18, BOTH pairs in one sweep (weights loaded once,
    // feeding 4 chains) ----
    u64 h1A[2][9], h1B[2][9];
    #pragma unroll
    for (int j = 0; j < 18; j += 2) {
        float hoA[2][2], hoB[2][2];
        #pragma unroll
        for (int s = 0; s < 2; s++) {
            const int jj = j + s;
            ulonglong2 w = sW1[jj];
            u64 bb = sb1[jj];
            u64 a0 = fma2(w.x, xA0, bb);
            u64 a1 = fma2(w.x, xA2, bb);
            u64 b0 = fma2(w.x, xB0, bb);
            u64 b1v = fma2(w.x, xB2, bb);
            a0 = fma2(w.y, xA1, a0);
            a1 = fma2(w.y, xA3, a1);
            b0 = fma2(w.y, xB1, b0);
            b1v = fma2(w.y, xB3, b1v);
            hoA[s][0] = fmaxf(hadd(a0), 0.0f);
            hoA[s][1] = fmaxf(hadd(a1), 0.0f);
            hoB[s][0] = fmaxf(hadd(b0), 0.0f);
            hoB[s][1] = fmaxf(hadd(b1v), 0.0f);
        }
        h1A[0][j / 2] = pack2(hoA[0][0], hoA[1][0]);
        h1A[1][j / 2] = pack2(hoA[0][1], hoA[1][1]);
        h1B[0][j / 2] = pack2(hoB[0][0], hoB[1][0]);
        h1B[1][j / 2] = pack2(hoB[0][1], hoB[1][1]);
    }

    // ---- Layer 2: 18 -> 36, BOTH pairs in one sweep (each LDS feeds 4
    // FFMA2 chains) ----
    u64 h2A[2][18], h2B[2][18];
    #pragma unroll 2
    for (int j = 0; j < 36; j += 2) {
        float hoA[2][2], hoB[2][2];
        #pragma unroll
        for (int s = 0; s < 2; s++) {
            const int jj = j + s;
            u64 bb = sb2[jj];
            u64 a0 = bb, a1 = bb, b0 = bb, b1v = bb;
            #pragma unroll
            for (int q = 0; q < 4; q++) {
                ulonglong2 w = sW2[jj * 4 + q];
                a0 = fma2(w.x, h1A[0][2 * q], a0);
                a1 = fma2(w.x, h1A[1][2 * q], a1);
                b0 = fma2(w.x, h1B[0][2 * q], b0);
                b1v = fma2(w.x, h1B[1][2 * q], b1v);
                a0 = fma2(w.y, h1A[0][2 * q + 1], a0);
                a1 = fma2(w.y, h1A[1][2 * q + 1], a1);
                b0 = fma2(w.y, h1B[0][2 * q + 1], b0);
                b1v = fma2(w.y, h1B[1][2 * q + 1], b1v);
            }
            u64 wt = sW2t[jj];
            a0 = fma2(wt, h1A[0][8], a0);
            a1 = fma2(wt, h1A[1][8], a1);
            b0 = fma2(wt, h1B[0][8], b0);
            b1v = fma2(wt, h1B[1][8], b1v);
            hoA[s][0] = fmaxf(hadd(a0), 0.0f);
            hoA[s][1] = fmaxf(hadd(a1), 0.0f);
            hoB[s][0] = fmaxf(hadd(b0), 0.0f);
            hoB[s][1] = fmaxf(hadd(b1v), 0.0f);
        }
        h2A[0][j / 2] = pack2(hoA[0][0], hoA[1][0]);
        h2A[1][j / 2] = pack2(hoA[0][1], hoA[1][1]);
        h2B[0][j / 2] = pack2(hoB[0][0], hoB[1][0]);
        h2B[1][j / 2] = pack2(hoB[0][1], hoB[1][1]);
    }

    // ---- Layers 3+4 fused (constant-port weights): 36 -> 36 -> 1 ----
    // One row per iteration; 4 accumulator chains. W3 read exactly once.
    float v0 = cP.b4, v1 = v0, v2 = v0, v3 = v0;
    #pragma unroll 4
    for (int j = 0; j < 36; j++) {
        u64 bb = pack2(cP.b3[j], 0.0f);
        u64 a0 = bb, a1 = bb, a2 = bb, a3 = bb;
        #pragma unroll
        for (int q = 0; q < 9; q++) {
            ulonglong2 w = cP.W3[j * 9 + q];
            a0 = fma2(w.x, h2A[0][2 * q], a0);
            a1 = fma2(w.x, h2A[1][2 * q], a1);
            a2 = fma2(w.x, h2B[0][2 * q], a2);
            a3 = fma2(w.x, h2B[1][2 * q], a3);
            a0 = fma2(w.y, h2A[0][2 * q + 1], a0);
            a1 = fma2(w.y, h2A[1][2 * q + 1], a1);
            a2 = fma2(w.y, h2B[0][2 * q + 1], a2);
            a3 = fma2(w.y, h2B[1][2 * q + 1], a3);
        }
        float w4 = cP.W4[j];
        v0 = fmaf(w4, fmaxf(hadd(a0), 0.0f), v0);
        v1 = fmaf(w4, fmaxf(hadd(a1), 0.0f), v1);
        v2 = fmaf(w4, fmaxf(hadd(a2), 0.0f), v2);
        v3 = fmaf(w4, fmaxf(hadd(a3), 0.0f), v3);
    }

    // (K,2) int32 pairs: column index at odd positions
    const int4 p01 = *reinterpret_cast<const int4*>(tix + 2 * (size_t)k0);
    const int4 p23 = *reinterpret_cast<const int4*>(tix + 2 * (size_t)k0 + 4);
    if ((unsigned)p01.y < NCOLS) atomicMaxF(out + p01.y, v0);
    if ((unsigned)p01.w < NCOLS) atomicMaxF(out + p01.w, v1);
    if ((unsigned)p23.y < NCOLS) atomicMaxF(out + p23.y, v2);
    if ((unsigned)p23.w < NCOLS) atomicMaxF(out + p23.w, v3);
}

extern "C" void kernel_launch(void* const* d_in, const int* in_sizes, int n_in,
                              void* d_out, int out_size) {
    const float* x   = (const float*)d_in[0];
    const int*   tix = (const int*)d_in[1];
    const float* W1 = (const float*)d_in[2];
    const float* b1 = (const float*)d_in[3];
    const float* W2 = (const float*)d_in[4];
    const float* b2 = (const float*)d_in[5];
    const float* W3 = (const float*)d_in[6];
    const float* b3 = (const float*)d_in[7];
    const float* W4 = (const float*)d_in[8];
    const float* b4 = (const float*)d_in[9];
    float* out = (float*)d_out;

    // Node 1: init output + gather layer-3/4 params into device staging.
    int nInit = out_size > 1369 ? out_size : 1369;
    init_pack_kernel<<<(nInit + 255) / 256, 256>>>(out, out_size, W3, b3, W4, b4);

    // Node 2: ONE memcpy staging -> constant bank.
    void* stageAddr = nullptr;
    cudaGetSymbolAddress(&stageAddr, gStage);
    cudaMemcpyToSymbolAsync(cP, stageAddr, sizeof(CParams), 0,
                            cudaMemcpyDeviceToDevice);

    // Node 3: main kernel.
    const int nthreads = KTOT / 4;                 // 4 columns per thread
    mlp_scatter_kernel<<<(nthreads + 127) / 128, 128>>>(
        x, tix, W1, b1, W2, b2, out);
}